// round 1
// baseline (speedup 1.0000x reference)
#include <cuda_runtime.h>
#include <cstdint>

#define N_NODES 100000

// ---------------- scratch (alloc-free rule: __device__ globals) ----------------
__device__ __align__(16) float g_deg [N_NODES];
__device__ __align__(16) float g_dinv[N_NODES];
__device__ __align__(16) float g_XW1[(size_t)N_NODES * 128];
__device__ __align__(16) float g_H  [(size_t)N_NODES * 128];
__device__ __align__(16) float g_HW2[(size_t)N_NODES * 64];

// ---------------- helpers ----------------
__device__ __forceinline__ void red_add4(float* addr, float a, float b, float c, float d) {
    asm volatile("red.global.add.v4.f32 [%0], {%1, %2, %3, %4};"
                 :: "l"(addr), "f"(a), "f"(b), "f"(c), "f"(d) : "memory");
}

// ---------------- zero ----------------
__global__ void zero_kernel(float* __restrict__ p, size_t n4) {
    size_t i = (size_t)blockIdx.x * blockDim.x + threadIdx.x;
    size_t stride = (size_t)gridDim.x * blockDim.x;
    float4* p4 = (float4*)p;
    for (size_t k = i; k < n4; k += stride) p4[k] = make_float4(0.f, 0.f, 0.f, 0.f);
}

// ---------------- degrees ----------------
__global__ void deg_kernel(const int* __restrict__ rows, int nE) {
    int i = blockIdx.x * blockDim.x + threadIdx.x;
    if (i < nE) atomicAdd(&g_deg[rows[i]], 1.0f);
}

__global__ void dinv_kernel() {
    int i = blockIdx.x * blockDim.x + threadIdx.x;
    if (i < N_NODES) {
        float d = g_deg[i];
        // deg >= 1 always (self loops), clip is a formality
        g_dinv[i] = rsqrtf(fmaxf(d, 1e-24f));
    }
}

// ---------------- SGEMM: C[M,N] = op(A)[M,K] @ B[K,N] ----------------
// A row-major stride K, B row-major stride N. RELU applies relu on A load.
template <int BM, int BN, int BK, int TM, int TN, bool RELU>
__global__ __launch_bounds__((BM / TM) * (BN / TN))
void sgemm_kernel(int M, int N, int K,
                  const float* __restrict__ A,
                  const float* __restrict__ B,
                  float* __restrict__ C) {
    constexpr int THREADS = (BM / TM) * (BN / TN);
    __shared__ float As[BK][BM];
    __shared__ float Bs[BK][BN];

    const int tid = threadIdx.x;
    const int tx  = tid % (BN / TN);
    const int ty  = tid / (BN / TN);
    const int rowBase = blockIdx.y * BM;
    const int colBase = blockIdx.x * BN;

    float acc[TM][TN];
#pragma unroll
    for (int i = 0; i < TM; i++)
#pragma unroll
        for (int j = 0; j < TN; j++) acc[i][j] = 0.f;

    for (int k0 = 0; k0 < K; k0 += BK) {
        // load A tile (BM x BK), transpose into As[k][m]
#pragma unroll
        for (int i = tid * 4; i < BM * BK; i += THREADS * 4) {
            int r = i / BK;
            int c = i % BK;
            float4 v = make_float4(0.f, 0.f, 0.f, 0.f);
            int gr = rowBase + r;
            if (gr < M) v = *(const float4*)(A + (size_t)gr * K + k0 + c);
            if (RELU) {
                v.x = fmaxf(v.x, 0.f); v.y = fmaxf(v.y, 0.f);
                v.z = fmaxf(v.z, 0.f); v.w = fmaxf(v.w, 0.f);
            }
            As[c + 0][r] = v.x; As[c + 1][r] = v.y;
            As[c + 2][r] = v.z; As[c + 3][r] = v.w;
        }
        // load B tile (BK x BN) — K,N are exact multiples, no guard needed
#pragma unroll
        for (int i = tid * 4; i < BK * BN; i += THREADS * 4) {
            int r = i / BN;
            int c = i % BN;
            *(float4*)&Bs[r][c] = *(const float4*)(B + (size_t)(k0 + r) * N + colBase + c);
        }
        __syncthreads();

#pragma unroll
        for (int kk = 0; kk < BK; kk++) {
            float ar[TM], br[TN];
#pragma unroll
            for (int i = 0; i < TM; i++) ar[i] = As[kk][ty * TM + i];
#pragma unroll
            for (int j = 0; j < TN; j++) br[j] = Bs[kk][tx * TN + j];
#pragma unroll
            for (int i = 0; i < TM; i++)
#pragma unroll
                for (int j = 0; j < TN; j++) acc[i][j] += ar[i] * br[j];
        }
        __syncthreads();
    }

#pragma unroll
    for (int i = 0; i < TM; i++) {
        int gr = rowBase + ty * TM + i;
        if (gr < M) {
#pragma unroll
            for (int j = 0; j < TN; j += 4) {
                *(float4*)(C + (size_t)gr * N + colBase + tx * TN + j) =
                    make_float4(acc[i][j], acc[i][j + 1], acc[i][j + 2], acc[i][j + 3]);
            }
        }
    }
}

// ---------------- SPMM: dst[row] += w_e * src[col], width 128 (warp/edge) ----------------
__global__ void spmm_w128(const int* __restrict__ rows, const int* __restrict__ cols,
                          const float* __restrict__ src, float* __restrict__ dst, int nE) {
    int t = blockIdx.x * blockDim.x + threadIdx.x;
    int e = t >> 5;
    int lane = t & 31;
    if (e >= nE) return;
    int r = __ldg(&rows[e]);
    int c = __ldg(&cols[e]);
    float w = g_dinv[r] * g_dinv[c];
    float4 v = ((const float4*)(src + (size_t)c * 128))[lane];
    float* d = dst + (size_t)r * 128 + lane * 4;
    red_add4(d, w * v.x, w * v.y, w * v.z, w * v.w);
}

// ---------------- SPMM width 64 (16 lanes per edge) ----------------
__global__ void spmm_w64(const int* __restrict__ rows, const int* __restrict__ cols,
                         const float* __restrict__ src, float* __restrict__ dst, int nE) {
    int t = blockIdx.x * blockDim.x + threadIdx.x;
    int e = t >> 4;
    int lane = t & 15;
    if (e >= nE) return;
    int r = __ldg(&rows[e]);
    int c = __ldg(&cols[e]);
    float w = g_dinv[r] * g_dinv[c];
    float4 v = ((const float4*)(src + (size_t)c * 64))[lane];
    float* d = dst + (size_t)r * 64 + lane * 4;
    red_add4(d, w * v.x, w * v.y, w * v.z, w * v.w);
}

// ---------------- launch ----------------
extern "C" void kernel_launch(void* const* d_in, const int* in_sizes, int n_in,
                              void* d_out, int out_size) {
    const float* X  = (const float*)d_in[0];
    const float* W1 = (const float*)d_in[1];
    const float* W2 = (const float*)d_in[2];
    const int* er   = (const int*)d_in[3];
    const int* ec   = (const int*)d_in[4];
    float* out = (float*)d_out;

    const int M  = in_sizes[0] / 256;   // 100000
    const int nE = in_sizes[3];         // 1700000

    float *p_deg, *p_dinv, *p_xw1, *p_h, *p_hw2;
    cudaGetSymbolAddress((void**)&p_deg,  g_deg);
    cudaGetSymbolAddress((void**)&p_dinv, g_dinv);
    cudaGetSymbolAddress((void**)&p_xw1,  g_XW1);
    cudaGetSymbolAddress((void**)&p_h,    g_H);
    cudaGetSymbolAddress((void**)&p_hw2,  g_HW2);
    (void)p_dinv;

    // 1) zero deg, H, out
    zero_kernel<<<256, 256>>>(p_deg, (size_t)N_NODES / 4);
    zero_kernel<<<4096, 256>>>(p_h, (size_t)M * 128 / 4);
    zero_kernel<<<4096, 256>>>(out, (size_t)out_size / 4);

    // 2) degrees + d^-1/2
    deg_kernel<<<(nE + 255) / 256, 256>>>(er, nE);
    dinv_kernel<<<(N_NODES + 255) / 256, 256>>>();

    // 3) XW1 = X @ W1  (M x 256 x 128)
    {
        dim3 grid(1, (M + 127) / 128);
        sgemm_kernel<128, 128, 16, 8, 8, false><<<grid, 256>>>(M, 128, 256, X, W1, p_xw1);
    }

    // 4) H = A_hat @ XW1   (width 128, relu deferred to next GEMM's load)
    {
        long long threads = (long long)nE * 32;
        int blocks = (int)((threads + 255) / 256);
        spmm_w128<<<blocks, 256>>>(er, ec, p_xw1, p_h, nE);
    }

    // 5) HW2 = relu(H) @ W2  (M x 128 x 64)
    {
        dim3 grid(1, (M + 127) / 128);
        sgemm_kernel<128, 64, 16, 8, 4, true><<<grid, 256>>>(M, 64, 128, p_h, W2, p_hw2);
    }

    // 6) out = A_hat @ HW2  (width 64)
    {
        long long threads = (long long)nE * 16;
        int blocks = (int)((threads + 255) / 256);
        spmm_w64<<<blocks, 256>>>(er, ec, p_hw2, out, nE);
    }
}

// round 2
// speedup vs baseline: 1.4882x; 1.4882x over previous
#include <cuda_runtime.h>
#include <cstdint>

#define N_NODES 100000
#define NE_MAX  1700032
#define SCAN_B  1024
#define NUM_SB  ((N_NODES + SCAN_B - 1) / SCAN_B)   // 98

// ---------------- scratch (alloc-free rule: __device__ globals) ----------------
__device__ int   g_deg   [N_NODES];
__device__ float g_dinv  [N_NODES];
__device__ int   g_rowptr[N_NODES + 1];
__device__ int   g_cursor[N_NODES];
__device__ int   g_bsum  [128];
__device__ __align__(16) int   g_col_s[NE_MAX];
__device__ __align__(16) float g_w_s  [NE_MAX];
__device__ __align__(16) float g_XW1[(size_t)N_NODES * 128];
__device__ __align__(16) float g_H  [(size_t)N_NODES * 128];
__device__ __align__(16) float g_HW2[(size_t)N_NODES * 64];

// ---------------- zero deg ----------------
__global__ void zero_deg_kernel() {
    int i = blockIdx.x * blockDim.x + threadIdx.x;
    if (i < N_NODES) g_deg[i] = 0;
}

// ---------------- degree histogram ----------------
__global__ void deg_kernel(const int* __restrict__ rows, int nE) {
    int i = blockIdx.x * blockDim.x + threadIdx.x;
    if (i < nE) atomicAdd(&g_deg[rows[i]], 1);
}

__global__ void dinv_kernel() {
    int i = blockIdx.x * blockDim.x + threadIdx.x;
    if (i < N_NODES) g_dinv[i] = rsqrtf((float)max(g_deg[i], 1));
}

// ---------------- scan: block-level exclusive scan of degrees ----------------
__global__ __launch_bounds__(SCAN_B) void scanA_kernel() {
    __shared__ int s[SCAN_B];
    int tid = threadIdx.x;
    int i = blockIdx.x * SCAN_B + tid;
    int v = (i < N_NODES) ? g_deg[i] : 0;
    s[tid] = v;
    __syncthreads();
#pragma unroll
    for (int off = 1; off < SCAN_B; off <<= 1) {
        int t = (tid >= off) ? s[tid - off] : 0;
        __syncthreads();
        s[tid] += t;
        __syncthreads();
    }
    if (i < N_NODES) g_rowptr[i] = s[tid] - v;   // exclusive, block-local
    if (tid == SCAN_B - 1) g_bsum[blockIdx.x] = s[tid];
}

__global__ void scanB_kernel(int nb) {   // single block of 128 threads
    __shared__ int s[128];
    int tid = threadIdx.x;
    int v = (tid < nb) ? g_bsum[tid] : 0;
    s[tid] = v;
    __syncthreads();
#pragma unroll
    for (int off = 1; off < 128; off <<= 1) {
        int t = (tid >= off) ? s[tid - off] : 0;
        __syncthreads();
        s[tid] += t;
        __syncthreads();
    }
    if (tid < nb) g_bsum[tid] = s[tid] - v;      // exclusive block offsets
}

__global__ __launch_bounds__(SCAN_B) void scanC_kernel(int nE) {
    int i = blockIdx.x * SCAN_B + threadIdx.x;
    if (i < N_NODES) {
        int rp = g_rowptr[i] + g_bsum[blockIdx.x];
        g_rowptr[i] = rp;
        g_cursor[i] = rp;
    }
    if (i == 0) g_rowptr[N_NODES] = nE;
}

// ---------------- scatter edges into CSR, pre-baking edge weights ----------------
__global__ void scatter_kernel(const int* __restrict__ rows, const int* __restrict__ cols,
                               int nE) {
    int i = blockIdx.x * blockDim.x + threadIdx.x;
    if (i >= nE) return;
    int r = rows[i];
    int c = cols[i];
    int pos = atomicAdd(&g_cursor[r], 1);
    g_col_s[pos] = c;
    g_w_s[pos]   = g_dinv[r] * g_dinv[c];
}

// ---------------- SGEMM: C[M,N] = op(A)[M,K] @ B[K,N] ----------------
template <int BM, int BN, int BK, int TM, int TN, bool RELU>
__global__ __launch_bounds__((BM / TM) * (BN / TN))
void sgemm_kernel(int M, int N, int K,
                  const float* __restrict__ A,
                  const float* __restrict__ B,
                  float* __restrict__ C) {
    constexpr int THREADS = (BM / TM) * (BN / TN);
    __shared__ float As[BK][BM];
    __shared__ float Bs[BK][BN];

    const int tid = threadIdx.x;
    const int tx  = tid % (BN / TN);
    const int ty  = tid / (BN / TN);
    const int rowBase = blockIdx.y * BM;
    const int colBase = blockIdx.x * BN;

    float acc[TM][TN];
#pragma unroll
    for (int i = 0; i < TM; i++)
#pragma unroll
        for (int j = 0; j < TN; j++) acc[i][j] = 0.f;

    for (int k0 = 0; k0 < K; k0 += BK) {
#pragma unroll
        for (int i = tid * 4; i < BM * BK; i += THREADS * 4) {
            int r = i / BK;
            int c = i % BK;
            float4 v = make_float4(0.f, 0.f, 0.f, 0.f);
            int gr = rowBase + r;
            if (gr < M) v = *(const float4*)(A + (size_t)gr * K + k0 + c);
            if (RELU) {
                v.x = fmaxf(v.x, 0.f); v.y = fmaxf(v.y, 0.f);
                v.z = fmaxf(v.z, 0.f); v.w = fmaxf(v.w, 0.f);
            }
            As[c + 0][r] = v.x; As[c + 1][r] = v.y;
            As[c + 2][r] = v.z; As[c + 3][r] = v.w;
        }
#pragma unroll
        for (int i = tid * 4; i < BK * BN; i += THREADS * 4) {
            int r = i / BN;
            int c = i % BN;
            *(float4*)&Bs[r][c] = *(const float4*)(B + (size_t)(k0 + r) * N + colBase + c);
        }
        __syncthreads();

#pragma unroll
        for (int kk = 0; kk < BK; kk++) {
            float ar[TM], br[TN];
#pragma unroll
            for (int i = 0; i < TM; i++) ar[i] = As[kk][ty * TM + i];
#pragma unroll
            for (int j = 0; j < TN; j++) br[j] = Bs[kk][tx * TN + j];
#pragma unroll
            for (int i = 0; i < TM; i++)
#pragma unroll
                for (int j = 0; j < TN; j++) acc[i][j] += ar[i] * br[j];
        }
        __syncthreads();
    }

#pragma unroll
    for (int i = 0; i < TM; i++) {
        int gr = rowBase + ty * TM + i;
        if (gr < M) {
#pragma unroll
            for (int j = 0; j < TN; j += 4) {
                *(float4*)(C + (size_t)gr * N + colBase + tx * TN + j) =
                    make_float4(acc[i][j], acc[i][j + 1], acc[i][j + 2], acc[i][j + 3]);
            }
        }
    }
}

// ---------------- CSR SPMM, width 128: one warp per row ----------------
__global__ __launch_bounds__(256) void spmm_csr128(const float* __restrict__ src,
                                                   float* __restrict__ dst) {
    int row = blockIdx.x * 8 + (threadIdx.x >> 5);
    if (row >= N_NODES) return;
    int lane = threadIdx.x & 31;
    int e   = g_rowptr[row];
    int end = g_rowptr[row + 1];

    float4 acc = make_float4(0.f, 0.f, 0.f, 0.f);
    for (; e + 1 < end; e += 2) {
        int   c0 = g_col_s[e];
        float w0 = g_w_s[e];
        int   c1 = g_col_s[e + 1];
        float w1 = g_w_s[e + 1];
        float4 v0 = ((const float4*)(src + (size_t)c0 * 128))[lane];
        float4 v1 = ((const float4*)(src + (size_t)c1 * 128))[lane];
        acc.x += w0 * v0.x + w1 * v1.x;
        acc.y += w0 * v0.y + w1 * v1.y;
        acc.z += w0 * v0.z + w1 * v1.z;
        acc.w += w0 * v0.w + w1 * v1.w;
    }
    if (e < end) {
        int   c0 = g_col_s[e];
        float w0 = g_w_s[e];
        float4 v0 = ((const float4*)(src + (size_t)c0 * 128))[lane];
        acc.x += w0 * v0.x; acc.y += w0 * v0.y;
        acc.z += w0 * v0.z; acc.w += w0 * v0.w;
    }
    ((float4*)(dst + (size_t)row * 128))[lane] = acc;
}

// ---------------- CSR SPMM, width 64: one warp per row (float2/lane) ----------------
__global__ __launch_bounds__(256) void spmm_csr64(const float* __restrict__ src,
                                                  float* __restrict__ dst) {
    int row = blockIdx.x * 8 + (threadIdx.x >> 5);
    if (row >= N_NODES) return;
    int lane = threadIdx.x & 31;
    int e   = g_rowptr[row];
    int end = g_rowptr[row + 1];

    float2 acc = make_float2(0.f, 0.f);
    for (; e + 1 < end; e += 2) {
        int   c0 = g_col_s[e];
        float w0 = g_w_s[e];
        int   c1 = g_col_s[e + 1];
        float w1 = g_w_s[e + 1];
        float2 v0 = ((const float2*)(src + (size_t)c0 * 64))[lane];
        float2 v1 = ((const float2*)(src + (size_t)c1 * 64))[lane];
        acc.x += w0 * v0.x + w1 * v1.x;
        acc.y += w0 * v0.y + w1 * v1.y;
    }
    if (e < end) {
        int   c0 = g_col_s[e];
        float w0 = g_w_s[e];
        float2 v0 = ((const float2*)(src + (size_t)c0 * 64))[lane];
        acc.x += w0 * v0.x;
        acc.y += w0 * v0.y;
    }
    ((float2*)(dst + (size_t)row * 64))[lane] = acc;
}

// ---------------- launch ----------------
extern "C" void kernel_launch(void* const* d_in, const int* in_sizes, int n_in,
                              void* d_out, int out_size) {
    const float* X  = (const float*)d_in[0];
    const float* W1 = (const float*)d_in[1];
    const float* W2 = (const float*)d_in[2];
    const int* er   = (const int*)d_in[3];
    const int* ec   = (const int*)d_in[4];
    float* out = (float*)d_out;

    const int M  = in_sizes[0] / 256;   // 100000
    const int nE = in_sizes[3];         // 1700000

    float *p_xw1, *p_h, *p_hw2;
    cudaGetSymbolAddress((void**)&p_xw1, g_XW1);
    cudaGetSymbolAddress((void**)&p_h,   g_H);
    cudaGetSymbolAddress((void**)&p_hw2, g_HW2);

    // ---- CSR build ----
    zero_deg_kernel<<<(N_NODES + 255) / 256, 256>>>();
    deg_kernel<<<(nE + 255) / 256, 256>>>(er, nE);
    dinv_kernel<<<(N_NODES + 255) / 256, 256>>>();
    scanA_kernel<<<NUM_SB, SCAN_B>>>();
    scanB_kernel<<<1, 128>>>(NUM_SB);
    scanC_kernel<<<NUM_SB, SCAN_B>>>(nE);
    scatter_kernel<<<(nE + 255) / 256, 256>>>(er, ec, nE);

    // ---- GEMM1: XW1 = X @ W1  (M x 256 x 128) ----
    {
        dim3 grid(1, (M + 127) / 128);
        sgemm_kernel<128, 128, 16, 8, 8, false><<<grid, 256>>>(M, 128, 256, X, W1, p_xw1);
    }

    // ---- SPMM1: H = A_hat @ XW1 (width 128) ----
    spmm_csr128<<<(N_NODES + 7) / 8, 256>>>(p_xw1, p_h);

    // ---- GEMM2: HW2 = relu(H) @ W2  (M x 128 x 64) ----
    {
        dim3 grid(1, (M + 127) / 128);
        sgemm_kernel<128, 64, 16, 8, 4, true><<<grid, 256>>>(M, 64, 128, p_h, W2, p_hw2);
    }

    // ---- SPMM2: out = A_hat @ HW2 (width 64) ----
    spmm_csr64<<<(N_NODES + 7) / 8, 256>>>(p_hw2, out);
}

// round 3
// speedup vs baseline: 1.7881x; 1.2015x over previous
#include <cuda_runtime.h>
#include <cstdint>

#define N_NODES 100000
#define NE_MAX  1700032
#define SCAN_B  1024
#define NUM_SB  ((N_NODES + SCAN_B - 1) / SCAN_B)   // 98

// ---------------- scratch (alloc-free rule: __device__ globals) ----------------
__device__ int   g_deg   [N_NODES];
__device__ float g_dinv  [N_NODES];
__device__ int   g_rowptr[N_NODES + 1];
__device__ int   g_cursor[N_NODES];
__device__ int   g_bsum  [128];
__device__ __align__(16) int   g_col_s[NE_MAX];
__device__ __align__(16) float g_w_s  [NE_MAX];
__device__ __align__(16) float g_XW1[(size_t)N_NODES * 128];
__device__ __align__(16) float g_H  [(size_t)N_NODES * 128];
__device__ __align__(16) float g_HW2[(size_t)N_NODES * 64];

// ---------------- small helpers ----------------
__device__ __forceinline__ float tf32_rnd(float x) {
    float r;
    asm("cvt.rna.tf32.f32 %0, %1;" : "=f"(r) : "f"(x));
    return r;
}

__device__ __forceinline__ void mma_tf32(float c[4], const float a[4], const float b[2]) {
    asm volatile(
        "mma.sync.aligned.m16n8k8.row.col.f32.tf32.tf32.f32 "
        "{%0,%1,%2,%3}, {%4,%5,%6,%7}, {%8,%9}, {%0,%1,%2,%3};"
        : "+f"(c[0]), "+f"(c[1]), "+f"(c[2]), "+f"(c[3])
        : "r"(__float_as_uint(a[0])), "r"(__float_as_uint(a[1])),
          "r"(__float_as_uint(a[2])), "r"(__float_as_uint(a[3])),
          "r"(__float_as_uint(b[0])), "r"(__float_as_uint(b[1])));
}

__device__ __forceinline__ void cp_async16(void* smem_dst, const void* gsrc, bool valid) {
    uint32_t d = (uint32_t)__cvta_generic_to_shared(smem_dst);
    int sz = valid ? 16 : 0;
    asm volatile("cp.async.cg.shared.global [%0], [%1], 16, %2;"
                 :: "r"(d), "l"(gsrc), "r"(sz) : "memory");
}

// ---------------- CSR build ----------------
__global__ void zero_deg_kernel() {
    int i = blockIdx.x * blockDim.x + threadIdx.x;
    if (i < N_NODES) g_deg[i] = 0;
}

__global__ void deg_kernel(const int* __restrict__ rows, int nE) {
    int i = blockIdx.x * blockDim.x + threadIdx.x;
    if (i < nE) atomicAdd(&g_deg[rows[i]], 1);
}

__global__ void dinv_kernel() {
    int i = blockIdx.x * blockDim.x + threadIdx.x;
    if (i < N_NODES) g_dinv[i] = rsqrtf((float)max(g_deg[i], 1));
}

__global__ __launch_bounds__(SCAN_B) void scanA_kernel() {
    __shared__ int s[SCAN_B];
    int tid = threadIdx.x;
    int i = blockIdx.x * SCAN_B + tid;
    int v = (i < N_NODES) ? g_deg[i] : 0;
    s[tid] = v;
    __syncthreads();
#pragma unroll
    for (int off = 1; off < SCAN_B; off <<= 1) {
        int t = (tid >= off) ? s[tid - off] : 0;
        __syncthreads();
        s[tid] += t;
        __syncthreads();
    }
    if (i < N_NODES) g_rowptr[i] = s[tid] - v;
    if (tid == SCAN_B - 1) g_bsum[blockIdx.x] = s[tid];
}

__global__ void scanB_kernel(int nb) {
    __shared__ int s[128];
    int tid = threadIdx.x;
    int v = (tid < nb) ? g_bsum[tid] : 0;
    s[tid] = v;
    __syncthreads();
#pragma unroll
    for (int off = 1; off < 128; off <<= 1) {
        int t = (tid >= off) ? s[tid - off] : 0;
        __syncthreads();
        s[tid] += t;
        __syncthreads();
    }
    if (tid < nb) g_bsum[tid] = s[tid] - v;
}

__global__ __launch_bounds__(SCAN_B) void scanC_kernel(int nE) {
    int i = blockIdx.x * SCAN_B + threadIdx.x;
    if (i < N_NODES) {
        int rp = g_rowptr[i] + g_bsum[blockIdx.x];
        g_rowptr[i] = rp;
        g_cursor[i] = rp;
    }
    if (i == 0) g_rowptr[N_NODES] = nE;
}

__global__ void scatter_kernel(const int* __restrict__ rows, const int* __restrict__ cols,
                               int nE) {
    int i = blockIdx.x * blockDim.x + threadIdx.x;
    if (i >= nE) return;
    int r = rows[i];
    int c = cols[i];
    int pos = atomicAdd(&g_cursor[r], 1);
    g_col_s[pos] = c;
    g_w_s[pos]   = g_dinv[r] * g_dinv[c];
}

// ---------------- TF32 tensor-core GEMM (3xTF32): C = A @ B ----------------
// BM=128, BK=32, BN template (128 or 64). 256 threads = 8 warps (4 x 2).
// A row-major [M,K], B row-major [K,N], C row-major [M,N]. K % 32 == 0, N % BN == 0.
template <int BN>
__global__ __launch_bounds__(256)
void mma_gemm_kernel(int M, int N, int K,
                     const float* __restrict__ A,
                     const float* __restrict__ B,
                     float* __restrict__ C) {
    constexpr int BM = 128;
    constexpr int BK = 32;
    constexpr int AS = 36;          // A smem row stride (floats)
    constexpr int BS = BN + 8;      // B smem row stride (floats)
    constexpr int A_STAGE = BM * AS;
    constexpr int B_STAGE = BK * BS;
    constexpr int STAGE   = A_STAGE + B_STAGE;
    constexpr int WN = BN / 2;      // warp tile N (warps 4x2)
    constexpr int NT = WN / 8;      // n-tiles per warp
    constexpr int B_LD = (BK * BN / 4) / 256;  // float4 loads per thread for B

    extern __shared__ float smem[];

    const int tid    = threadIdx.x;
    const int lane   = tid & 31;
    const int wid    = tid >> 5;
    const int warp_m = wid & 3;
    const int warp_n = wid >> 2;
    const int g      = lane >> 2;   // 0..7
    const int q      = lane & 3;    // 0..3
    const int rowBase = blockIdx.y * BM;
    const int colBase = blockIdx.x * BN;

    float acc[2][NT][4];
#pragma unroll
    for (int mt = 0; mt < 2; mt++)
#pragma unroll
        for (int nt = 0; nt < NT; nt++)
#pragma unroll
            for (int r = 0; r < 4; r++) acc[mt][nt][r] = 0.f;

    const int NITER = K / BK;

    // ---- tile loader (cp.async) ----
    auto load_tile = [&](int stage, int k0) {
        float* sA = smem + stage * STAGE;
        float* sB = sA + A_STAGE;
        // A: 128 x 32 floats = 1024 float4, 4 per thread
#pragma unroll
        for (int i = 0; i < 4; i++) {
            int e = tid + i * 256;
            int r = e >> 3;             // 8 float4 per row
            int c4 = (e & 7) * 4;
            int gr = rowBase + r;
            cp_async16(sA + r * AS + c4, A + (size_t)gr * K + k0 + c4, gr < M);
        }
        // B: 32 x BN floats
#pragma unroll
        for (int i = 0; i < B_LD; i++) {
            int e = tid + i * 256;
            int r = e / (BN / 4);
            int c4 = (e % (BN / 4)) * 4;
            cp_async16(sB + r * BS + c4, B + (size_t)(k0 + r) * N + colBase + c4, true);
        }
        asm volatile("cp.async.commit_group;" ::: "memory");
    };

    load_tile(0, 0);

    for (int it = 0; it < NITER; ++it) {
        int cur = it & 1;
        if (it + 1 < NITER) {
            load_tile(cur ^ 1, (it + 1) * BK);
            asm volatile("cp.async.wait_group 1;" ::: "memory");
        } else {
            asm volatile("cp.async.wait_group 0;" ::: "memory");
        }
        __syncthreads();

        const float* sA = smem + cur * STAGE;
        const float* sB = sA + A_STAGE;

#pragma unroll
        for (int ks = 0; ks < 4; ks++) {
            float ah[2][4], al[2][4];
#pragma unroll
            for (int mt = 0; mt < 2; mt++) {
                const float* ap = sA + (warp_m * 32 + mt * 16 + g) * AS + ks * 8 + q;
                float a0 = ap[0];
                float a1 = ap[8 * AS];
                float a2 = ap[4];
                float a3 = ap[8 * AS + 4];
                ah[mt][0] = tf32_rnd(a0); al[mt][0] = tf32_rnd(a0 - ah[mt][0]);
                ah[mt][1] = tf32_rnd(a1); al[mt][1] = tf32_rnd(a1 - ah[mt][1]);
                ah[mt][2] = tf32_rnd(a2); al[mt][2] = tf32_rnd(a2 - ah[mt][2]);
                ah[mt][3] = tf32_rnd(a3); al[mt][3] = tf32_rnd(a3 - ah[mt][3]);
            }
#pragma unroll
            for (int nt = 0; nt < NT; nt++) {
                const float* bp = sB + (ks * 8 + q) * BS + warp_n * WN + nt * 8 + g;
                float b0 = bp[0];
                float b1 = bp[4 * BS];
                float bh[2], bl[2];
                bh[0] = tf32_rnd(b0); bl[0] = tf32_rnd(b0 - bh[0]);
                bh[1] = tf32_rnd(b1); bl[1] = tf32_rnd(b1 - bh[1]);
#pragma unroll
                for (int mt = 0; mt < 2; mt++) {
                    mma_tf32(acc[mt][nt], ah[mt], bh);
                    mma_tf32(acc[mt][nt], al[mt], bh);
                    mma_tf32(acc[mt][nt], ah[mt], bl);
                }
            }
        }
        __syncthreads();
    }

    // ---- epilogue ----
#pragma unroll
    for (int mt = 0; mt < 2; mt++) {
        int r0 = rowBase + warp_m * 32 + mt * 16 + g;
        int r1 = r0 + 8;
#pragma unroll
        for (int nt = 0; nt < NT; nt++) {
            int col = colBase + warp_n * WN + nt * 8 + 2 * q;
            if (r0 < M)
                *(float2*)(C + (size_t)r0 * N + col) = make_float2(acc[mt][nt][0], acc[mt][nt][1]);
            if (r1 < M)
                *(float2*)(C + (size_t)r1 * N + col) = make_float2(acc[mt][nt][2], acc[mt][nt][3]);
        }
    }
}

// ---------------- CSR SPMM, width 128: one warp per row (+ReLU on store) ----------------
__global__ __launch_bounds__(256) void spmm_csr128(const float* __restrict__ src,
                                                   float* __restrict__ dst) {
    int row = blockIdx.x * 8 + (threadIdx.x >> 5);
    if (row >= N_NODES) return;
    int lane = threadIdx.x & 31;
    int e   = g_rowptr[row];
    int end = g_rowptr[row + 1];

    float4 acc = make_float4(0.f, 0.f, 0.f, 0.f);
    for (; e + 1 < end; e += 2) {
        int   c0 = g_col_s[e];
        float w0 = g_w_s[e];
        int   c1 = g_col_s[e + 1];
        float w1 = g_w_s[e + 1];
        float4 v0 = ((const float4*)(src + (size_t)c0 * 128))[lane];
        float4 v1 = ((const float4*)(src + (size_t)c1 * 128))[lane];
        acc.x += w0 * v0.x + w1 * v1.x;
        acc.y += w0 * v0.y + w1 * v1.y;
        acc.z += w0 * v0.z + w1 * v1.z;
        acc.w += w0 * v0.w + w1 * v1.w;
    }
    if (e < end) {
        int   c0 = g_col_s[e];
        float w0 = g_w_s[e];
        float4 v0 = ((const float4*)(src + (size_t)c0 * 128))[lane];
        acc.x += w0 * v0.x; acc.y += w0 * v0.y;
        acc.z += w0 * v0.z; acc.w += w0 * v0.w;
    }
    // fused ReLU (H is only consumed as relu(H))
    acc.x = fmaxf(acc.x, 0.f); acc.y = fmaxf(acc.y, 0.f);
    acc.z = fmaxf(acc.z, 0.f); acc.w = fmaxf(acc.w, 0.f);
    ((float4*)(dst + (size_t)row * 128))[lane] = acc;
}

// ---------------- CSR SPMM, width 64: one warp per row ----------------
__global__ __launch_bounds__(256) void spmm_csr64(const float* __restrict__ src,
                                                  float* __restrict__ dst) {
    int row = blockIdx.x * 8 + (threadIdx.x >> 5);
    if (row >= N_NODES) return;
    int lane = threadIdx.x & 31;
    int e   = g_rowptr[row];
    int end = g_rowptr[row + 1];

    float2 acc = make_float2(0.f, 0.f);
    for (; e + 1 < end; e += 2) {
        int   c0 = g_col_s[e];
        float w0 = g_w_s[e];
        int   c1 = g_col_s[e + 1];
        float w1 = g_w_s[e + 1];
        float2 v0 = ((const float2*)(src + (size_t)c0 * 64))[lane];
        float2 v1 = ((const float2*)(src + (size_t)c1 * 64))[lane];
        acc.x += w0 * v0.x + w1 * v1.x;
        acc.y += w0 * v0.y + w1 * v1.y;
    }
    if (e < end) {
        int   c0 = g_col_s[e];
        float w0 = g_w_s[e];
        float2 v0 = ((const float2*)(src + (size_t)c0 * 64))[lane];
        acc.x += w0 * v0.x;
        acc.y += w0 * v0.y;
    }
    ((float2*)(dst + (size_t)row * 64))[lane] = acc;
}

// ---------------- launch ----------------
extern "C" void kernel_launch(void* const* d_in, const int* in_sizes, int n_in,
                              void* d_out, int out_size) {
    const float* X  = (const float*)d_in[0];
    const float* W1 = (const float*)d_in[1];
    const float* W2 = (const float*)d_in[2];
    const int* er   = (const int*)d_in[3];
    const int* ec   = (const int*)d_in[4];
    float* out = (float*)d_out;

    const int M  = in_sizes[0] / 256;   // 100000
    const int nE = in_sizes[3];         // 1700000

    float *p_xw1, *p_h, *p_hw2;
    cudaGetSymbolAddress((void**)&p_xw1, g_XW1);
    cudaGetSymbolAddress((void**)&p_h,   g_H);
    cudaGetSymbolAddress((void**)&p_hw2, g_HW2);

    // smem sizes for the two GEMM variants
    const int smem1 = 2 * (128 * 36 + 32 * (128 + 8)) * 4;  // 71680
    const int smem2 = 2 * (128 * 36 + 32 * (64 + 8)) * 4;   // 55296
    static bool attr_set = false;
    if (!attr_set) {
        cudaFuncSetAttribute(mma_gemm_kernel<128>,
                             cudaFuncAttributeMaxDynamicSharedMemorySize, smem1);
        cudaFuncSetAttribute(mma_gemm_kernel<64>,
                             cudaFuncAttributeMaxDynamicSharedMemorySize, smem2);
        attr_set = true;
    }

    // ---- CSR build ----
    zero_deg_kernel<<<(N_NODES + 255) / 256, 256>>>();
    deg_kernel<<<(nE + 255) / 256, 256>>>(er, nE);
    dinv_kernel<<<(N_NODES + 255) / 256, 256>>>();
    scanA_kernel<<<NUM_SB, SCAN_B>>>();
    scanB_kernel<<<1, 128>>>(NUM_SB);
    scanC_kernel<<<NUM_SB, SCAN_B>>>(nE);
    scatter_kernel<<<(nE + 255) / 256, 256>>>(er, ec, nE);

    // ---- GEMM1: XW1 = X @ W1  (M x 256 x 128), tf32x3 tensor-core ----
    {
        dim3 grid(1, (M + 127) / 128);
        mma_gemm_kernel<128><<<grid, 256, smem1>>>(M, 128, 256, X, W1, p_xw1);
    }

    // ---- SPMM1: H = relu(A_hat @ XW1) (width 128) ----
    spmm_csr128<<<(N_NODES + 7) / 8, 256>>>(p_xw1, p_h);

    // ---- GEMM2: HW2 = H @ W2  (M x 128 x 64), tf32x3 tensor-core ----
    {
        dim3 grid(1, (M + 127) / 128);
        mma_gemm_kernel<64><<<grid, 256, smem2>>>(M, 64, 128, p_h, W2, p_hw2);
    }

    // ---- SPMM2: out = A_hat @ HW2 (width 64) ----
    spmm_csr64<<<(N_NODES + 7) / 8, 256>>>(p_hw2, out);
}